// round 12
// baseline (speedup 1.0000x reference)
// Linear1d: out = (x @ W^T) / sqrt(2048) + 0.1*b
// fp16 single-term HMMA, 3-stage cp.async pipeline, 2 CTAs/SM (R9 structure),
// + B-fragment software pipelining across ks-steps.
#include <cuda_runtime.h>
#include <cuda_fp16.h>
#include <cstdint>

#define XN 16384
#define KD 2048
#define ON 2048

static constexpr int BM = 128, BN = 128, BK = 64;  // BK fp16 elems (128B rows)
static constexpr int NCH = KD / BK;                // 32
static constexpr int PL_A = 0;                      // 128 rows x 128B
static constexpr int PL_B = 16384;                  // 128 rows x 128B
static constexpr int STAGE = 32768;
static constexpr int NSTG = 3;
static constexpr int SMEM_TOTAL = NSTG * STAGE;     // 96 KB -> 2 CTAs/SM

// fp16 planes (device scratch)
__device__ __half hA[(size_t)XN * KD];  // 67 MB
__device__ __half hB[(size_t)ON * KD];  // 8.4 MB

// ---------------- helpers ----------------
__device__ __forceinline__ uint32_t smem_u32(const void* p) {
    uint32_t a;
    asm("{ .reg .u64 t; cvta.to.shared.u64 t, %1; cvt.u32.u64 %0, t; }" : "=r"(a) : "l"(p));
    return a;
}
__device__ __forceinline__ void cp16(uint32_t dst, const void* src) {
    asm volatile("cp.async.cg.shared.global [%0], [%1], 16;" :: "r"(dst), "l"(src));
}
__device__ __forceinline__ void ldm_x4(uint32_t* r, uint32_t addr) {
    asm volatile("ldmatrix.sync.aligned.m8n8.x4.shared.b16 {%0,%1,%2,%3}, [%4];"
                 : "=r"(r[0]), "=r"(r[1]), "=r"(r[2]), "=r"(r[3])
                 : "r"(addr));
}
__device__ __forceinline__ void mma_f16(float* c, const uint32_t* a, const uint32_t* b) {
    asm volatile(
        "mma.sync.aligned.m16n8k16.row.col.f32.f16.f16.f32 "
        "{%0,%1,%2,%3}, {%4,%5,%6,%7}, {%8,%9}, {%0,%1,%2,%3};"
        : "+f"(c[0]), "+f"(c[1]), "+f"(c[2]), "+f"(c[3])
        : "r"(a[0]), "r"(a[1]), "r"(a[2]), "r"(a[3]), "r"(b[0]), "r"(b[1]));
}

// ---------------- convert: fp32 -> fp16 plane ----------------
__global__ void __launch_bounds__(256) convert_kernel(const float* __restrict__ src,
                                                      int n4, int which) {
    size_t i = (size_t)blockIdx.x * blockDim.x + threadIdx.x;
    if (i >= (size_t)n4) return;
    __half* dst = which ? hB : hA;
    float4 v = ((const float4*)src)[i];
    __half2 p0 = __floats2half2_rn(v.x, v.y);
    __half2 p1 = __floats2half2_rn(v.z, v.w);
    uint2 o;
    o.x = *(const uint32_t*)&p0;
    o.y = *(const uint32_t*)&p1;
    ((uint2*)dst)[i] = o;
}

// ---------------- stage loader: 2 planes x 128 rows x 128B ----------------
__device__ __forceinline__ void load_stage(uint32_t sb, int st, int kc,
                                           int m0, int n0, int tid) {
    int r = tid & 127, h = tid >> 7;
    uint32_t base = sb + (uint32_t)st * STAGE;
    uint32_t sw = (uint32_t)((r & 7) << 4);  // SW128 xor
    const __half* sA = &hA[(size_t)(m0 + r) * KD + kc];
    const __half* sB = &hB[(size_t)(n0 + r) * KD + kc];
    uint32_t rb = base + (uint32_t)(r * 128);
#pragma unroll
    for (int j = 0; j < 4; j++) {
        int jc = h * 4 + j;                       // 16B chunk within 128B row
        uint32_t d = ((uint32_t)(jc * 16)) ^ sw;
        cp16(rb + PL_A + d, (const char*)sA + jc * 16);
        cp16(rb + PL_B + d, (const char*)sB + jc * 16);
    }
    asm volatile("cp.async.commit_group;" ::: "memory");
}

// ---------------- GEMM: 128x128 tile, 8 warps of 64x32, 2 CTAs/SM ----------------
__global__ void __launch_bounds__(256, 2) gemm_kernel(const float* __restrict__ bias,
                                                      float* __restrict__ out) {
    extern __shared__ char smem[];
    uint32_t sb = smem_u32(smem);
    int tid = threadIdx.x, l = tid & 31, wid = tid >> 5;
    int wm = wid & 1, wn = wid >> 1;  // 2 x 4 warp grid (64x32 each)
    int m0 = blockIdx.y * BM, n0 = blockIdx.x * BN;

    float acc[4][4][4];
#pragma unroll
    for (int i = 0; i < 4; i++)
#pragma unroll
        for (int j = 0; j < 4; j++)
#pragma unroll
            for (int q = 0; q < 4; q++) acc[i][j][q] = 0.f;

    load_stage(sb, 0, 0, m0, n0, tid);
    load_stage(sb, 1, BK, m0, n0, tid);

    // ldmatrix lane geometry: 128B rows, SW128 xor
    int g = l >> 3, lr = l & 7;
    uint32_t swx = (uint32_t)(lr << 4);
    uint32_t a_row = (uint32_t)(wm * 64 + ((g & 1) << 3) + lr);
    uint32_t a_kb0 = (uint32_t)((g >> 1) << 4);
    uint32_t b_row = (uint32_t)(wn * 32 + ((g >> 1) << 3) + lr);
    uint32_t b_kb0 = (uint32_t)((g & 1) << 4);

    for (int c = 0; c < NCH; c++) {
        if (c + 1 < NCH) asm volatile("cp.async.wait_group 1;" ::: "memory");
        else             asm volatile("cp.async.wait_group 0;" ::: "memory");
        __syncthreads();
        if (c + 2 < NCH) load_stage(sb, (c + 2) % 3, (c + 2) * BK, m0, n0, tid);

        uint32_t base = sb + (uint32_t)(c % 3) * STAGE;
        uint32_t abase = base + PL_A, bbase = base + PL_B;

        // B-fragment software pipeline across 4 ks-steps
        uint32_t Bf[2][2][4];  // [buf][nf][frag]
        {
            uint32_t bkb = b_kb0 ^ swx;
            ldm_x4(Bf[0][0], bbase + ((b_row +  0u) << 7) + bkb);
            ldm_x4(Bf[0][1], bbase + ((b_row + 16u) << 7) + bkb);
        }
#pragma unroll
        for (int ks = 0; ks < 4; ks++) {
            int cur = ks & 1, nxt = cur ^ 1;
            if (ks < 3) {
                uint32_t bkb = (((uint32_t)((ks + 1) * 32)) + b_kb0) ^ swx;
                ldm_x4(Bf[nxt][0], bbase + ((b_row +  0u) << 7) + bkb);
                ldm_x4(Bf[nxt][1], bbase + ((b_row + 16u) << 7) + bkb);
            }
            uint32_t A[4][4];
            uint32_t akb = (((uint32_t)(ks * 32)) + a_kb0) ^ swx;
#pragma unroll
            for (int mf = 0; mf < 4; mf++)
                ldm_x4(A[mf], abase + ((a_row + (uint32_t)(mf * 16)) << 7) + akb);
#pragma unroll
            for (int mf = 0; mf < 4; mf++)
#pragma unroll
                for (int nf = 0; nf < 4; nf++)
                    mma_f16(acc[mf][nf], A[mf], &Bf[cur][nf >> 1][(nf & 1) * 2]);
        }
    }

    // epilogue: scale + 0.1*bias, float2 stores
    const float S = 0.02209708691207961f;  // 1/sqrt(2048)
    int col_base = n0 + wn * 32 + (l & 3) * 2;
    int row_base = m0 + wm * 64 + (l >> 2);
#pragma unroll
    for (int mf = 0; mf < 4; mf++) {
#pragma unroll
        for (int nf = 0; nf < 4; nf++) {
            int colx = col_base + nf * 8;
            float2 bv = *(const float2*)(bias + colx);
            float2 v0, v1;
            v0.x = acc[mf][nf][0] * S + 0.1f * bv.x;
            v0.y = acc[mf][nf][1] * S + 0.1f * bv.y;
            v1.x = acc[mf][nf][2] * S + 0.1f * bv.x;
            v1.y = acc[mf][nf][3] * S + 0.1f * bv.y;
            size_t r0 = (size_t)(row_base + mf * 16) * ON + colx;
            *(float2*)(out + r0) = v0;
            *(float2*)(out + r0 + (size_t)8 * ON) = v1;
        }
    }
}

// ---------------- launch ----------------
extern "C" void kernel_launch(void* const* d_in, const int* in_sizes, int n_in,
                              void* d_out, int out_size) {
    (void)in_sizes; (void)n_in; (void)out_size;
    const float* x = (const float*)d_in[0];
    const float* w = (const float*)d_in[1];
    const float* b = (const float*)d_in[2];
    float* out = (float*)d_out;

    cudaFuncSetAttribute(gemm_kernel, cudaFuncAttributeMaxDynamicSharedMemorySize, SMEM_TOTAL);

    int nx4 = (XN * KD) / 4;  // 8388608
    int nw4 = (ON * KD) / 4;  // 1048576
    convert_kernel<<<nx4 / 256, 256>>>(x, nx4, 0);
    convert_kernel<<<nw4 / 256, 256>>>(w, nw4, 1);

    dim3 grid(ON / BN, XN / BM);  // (16, 128): n-tiles fastest for W reuse in L2
    gemm_kernel<<<grid, 256, SMEM_TOTAL>>>(b, out);
}

// round 16
// speedup vs baseline: 1.0752x; 1.0752x over previous
// Linear1d: out = (x @ W^T) / sqrt(2048) + 0.1*b
// fp16 single-term HMMA, 3-stage cp.async pipeline, 2 CTAs/SM (proven R9 engine)
// + R15's tiled pre-swizzled repack: loader copies contiguous 128B/thread.
#include <cuda_runtime.h>
#include <cuda_fp16.h>
#include <cstdint>

#define XN 16384
#define KD 2048
#define ON 2048

static constexpr int BM = 128, BN = 128, BK = 64;  // BK fp16 elems (128B rows)
static constexpr int NCH = KD / BK;                // 32
static constexpr int BLKB = 16384;                 // one (tile,chunk) block image
static constexpr int PL_A = 0;
static constexpr int PL_B = BLKB;
static constexpr int STAGE = 2 * BLKB;             // 32 KB
static constexpr int NSTG = 3;
static constexpr int SMEM_TOTAL = NSTG * STAGE;    // 96 KB -> 2 CTAs/SM

// Tiled & pre-swizzled fp16 planes (block = byte image of one smem plane):
// gAq[(mtile*NCH + ch)*8192 + r*64 + (jc^(r&7))*8] = x[mtile*128+r][ch*64 + jc*8 .. +7]
__device__ __half gAq[(size_t)XN * KD];  // 67 MB
__device__ __half gBq[(size_t)ON * KD];  // 8.4 MB

// ---------------- helpers ----------------
__device__ __forceinline__ uint32_t smem_u32(const void* p) {
    uint32_t a;
    asm("{ .reg .u64 t; cvta.to.shared.u64 t, %1; cvt.u32.u64 %0, t; }" : "=r"(a) : "l"(p));
    return a;
}
__device__ __forceinline__ void cp16(uint32_t dst, const void* src) {
    asm volatile("cp.async.cg.shared.global [%0], [%1], 16;" :: "r"(dst), "l"(src));
}
__device__ __forceinline__ void ldm_x4(uint32_t* r, uint32_t addr) {
    asm volatile("ldmatrix.sync.aligned.m8n8.x4.shared.b16 {%0,%1,%2,%3}, [%4];"
                 : "=r"(r[0]), "=r"(r[1]), "=r"(r[2]), "=r"(r[3])
                 : "r"(addr));
}
__device__ __forceinline__ void mma_f16(float* c, const uint32_t* a, const uint32_t* b) {
    asm volatile(
        "mma.sync.aligned.m16n8k16.row.col.f32.f16.f16.f32 "
        "{%0,%1,%2,%3}, {%4,%5,%6,%7}, {%8,%9}, {%0,%1,%2,%3};"
        : "+f"(c[0]), "+f"(c[1]), "+f"(c[2]), "+f"(c[3])
        : "r"(a[0]), "r"(a[1]), "r"(a[2]), "r"(a[3]), "r"(b[0]), "r"(b[1]));
}

// ---------------- repack: fp32 row -> tiled pre-swizzled fp16 blocks ----------------
__global__ void __launch_bounds__(256) repack_kernel(const float* __restrict__ src, int which) {
    int row = blockIdx.x, t = threadIdx.x;        // 256 threads: one per 8 elems
    int ch = t >> 3, jc = t & 7;                  // chunk 0..31, 16B slot 0..7
    const float4* s = (const float4*)(src + (size_t)row * KD + t * 8);
    float4 v0 = s[0], v1 = s[1];
    __half2 p0 = __floats2half2_rn(v0.x, v0.y);
    __half2 p1 = __floats2half2_rn(v0.z, v0.w);
    __half2 p2 = __floats2half2_rn(v1.x, v1.y);
    __half2 p3 = __floats2half2_rn(v1.z, v1.w);
    uint4 hv;
    hv.x = *(const uint32_t*)&p0; hv.y = *(const uint32_t*)&p1;
    hv.z = *(const uint32_t*)&p2; hv.w = *(const uint32_t*)&p3;
    int r = row & 127, r7 = row & 7;
    __half* dst = which ? gBq : gAq;
    size_t off_h = ((size_t)(row >> 7) * NCH + ch) * 8192 + (size_t)r * 64 + ((jc ^ r7) * 8);
    *(uint4*)(dst + off_h) = hv;
}

// ---------------- stage loader: thread copies contiguous 128B of a block ----------------
__device__ __forceinline__ void load_stage(uint32_t sb, int st, const char* blkA,
                                           const char* blkB, int L, int tid) {
    uint32_t base = sb + (uint32_t)st * STAGE;
    const char* src;
    uint32_t dst;
    if (tid < 128) { src = blkA + (size_t)L * BLKB + tid * 128;          dst = base + PL_A + tid * 128; }
    else           { src = blkB + (size_t)L * BLKB + (tid - 128) * 128;  dst = base + PL_B + (tid - 128) * 128; }
#pragma unroll
    for (int j = 0; j < 8; j++)
        cp16(dst + j * 16, src + j * 16);
    asm volatile("cp.async.commit_group;" ::: "memory");
}

// ---------------- GEMM: 128x128 tile, 8 warps of 64x32, 2 CTAs/SM ----------------
__global__ void __launch_bounds__(256, 2) gemm_kernel(const float* __restrict__ bias,
                                                      float* __restrict__ out) {
    extern __shared__ char smem[];
    uint32_t sb = smem_u32(smem);
    int tid = threadIdx.x, l = tid & 31, wid = tid >> 5;
    int wm = wid & 1, wn = wid >> 1;  // 2 x 4 warp grid (64x32 each)
    int m0 = blockIdx.y * BM, n0 = blockIdx.x * BN;
    const char* blkA = (const char*)gAq + ((size_t)(m0 >> 7) * NCH) * BLKB;
    const char* blkB = (const char*)gBq + ((size_t)(n0 >> 7) * NCH) * BLKB;

    float acc[4][4][4];
#pragma unroll
    for (int i = 0; i < 4; i++)
#pragma unroll
        for (int j = 0; j < 4; j++)
#pragma unroll
            for (int q = 0; q < 4; q++) acc[i][j][q] = 0.f;

    load_stage(sb, 0, blkA, blkB, 0, tid);
    load_stage(sb, 1, blkA, blkB, 1, tid);

    // ldmatrix lane geometry: 128B rows, SW128 xor (image pre-swizzled by repack)
    int g = l >> 3, lr = l & 7;
    uint32_t swx = (uint32_t)(lr << 4);
    uint32_t a_row = (uint32_t)(wm * 64 + ((g & 1) << 3) + lr);
    uint32_t a_kb0 = (uint32_t)((g >> 1) << 4);
    uint32_t b_row = (uint32_t)(wn * 32 + ((g >> 1) << 3) + lr);
    uint32_t b_kb0 = (uint32_t)((g & 1) << 4);

    for (int c = 0; c < NCH; c++) {
        if (c + 1 < NCH) asm volatile("cp.async.wait_group 1;" ::: "memory");
        else             asm volatile("cp.async.wait_group 0;" ::: "memory");
        __syncthreads();
        if (c + 2 < NCH) load_stage(sb, (c + 2) % 3, blkA, blkB, c + 2, tid);

        uint32_t base = sb + (uint32_t)(c % 3) * STAGE;
#pragma unroll
        for (int ks = 0; ks < 4; ks++) {  // four k16 steps per 64-elem chunk
            uint32_t A[4][4], B[2][4];
            uint32_t akb = (((uint32_t)(ks * 32)) + a_kb0) ^ swx;
            uint32_t bkb = (((uint32_t)(ks * 32)) + b_kb0) ^ swx;
#pragma unroll
            for (int mf = 0; mf < 4; mf++)
                ldm_x4(A[mf], base + PL_A + ((a_row + (uint32_t)(mf * 16)) << 7) + akb);
#pragma unroll
            for (int nf = 0; nf < 2; nf++)
                ldm_x4(B[nf], base + PL_B + ((b_row + (uint32_t)(nf * 16)) << 7) + bkb);
#pragma unroll
            for (int mf = 0; mf < 4; mf++)
#pragma unroll
                for (int nf = 0; nf < 4; nf++)
                    mma_f16(acc[mf][nf], A[mf], &B[nf >> 1][(nf & 1) * 2]);
        }
    }

    // epilogue: scale + 0.1*bias, float2 stores
    const float S = 0.02209708691207961f;  // 1/sqrt(2048)
    int col_base = n0 + wn * 32 + (l & 3) * 2;
    int row_base = m0 + wm * 64 + (l >> 2);
#pragma unroll
    for (int mf = 0; mf < 4; mf++) {
#pragma unroll
        for (int nf = 0; nf < 4; nf++) {
            int colx = col_base + nf * 8;
            float2 bv = *(const float2*)(bias + colx);
            float2 v0, v1;
            v0.x = acc[mf][nf][0] * S + 0.1f * bv.x;
            v0.y = acc[mf][nf][1] * S + 0.1f * bv.y;
            v1.x = acc[mf][nf][2] * S + 0.1f * bv.x;
            v1.y = acc[mf][nf][3] * S + 0.1f * bv.y;
            size_t r0 = (size_t)(row_base + mf * 16) * ON + colx;
            *(float2*)(out + r0) = v0;
            *(float2*)(out + r0 + (size_t)8 * ON) = v1;
        }
    }
}

// ---------------- launch ----------------
extern "C" void kernel_launch(void* const* d_in, const int* in_sizes, int n_in,
                              void* d_out, int out_size) {
    (void)in_sizes; (void)n_in; (void)out_size;
    const float* x = (const float*)d_in[0];
    const float* w = (const float*)d_in[1];
    const float* b = (const float*)d_in[2];
    float* out = (float*)d_out;

    cudaFuncSetAttribute(gemm_kernel, cudaFuncAttributeMaxDynamicSharedMemorySize, SMEM_TOTAL);

    repack_kernel<<<XN, 256>>>(x, 0);
    repack_kernel<<<ON, 256>>>(w, 1);

    dim3 grid(ON / BN, XN / BM);  // (16, 128): n-tiles fastest for W reuse in L2
    gemm_kernel<<<grid, 256, SMEM_TOTAL>>>(b, out);
}